// round 14
// baseline (speedup 1.0000x reference)
#include <cuda_runtime.h>
#include <cuda_fp16.h>
#include <cstdint>

#define N_NODES 100000
#define N_EDGES 3200000
#define N_RELS  8
#define F_DIM   64

#define SCAN_BLK 1024
#define SCAN_NBLK ((N_NODES + SCAN_BLK - 1) / SCAN_BLK)   // 98

#define EBLOCKS ((N_EDGES + 255) / 256)                   // 12500
#define WCONV_BLOCKS ((N_RELS * 64 * 64 + 255) / 256)     // 128
#define XW_BLOCKS ((N_NODES + 63) / 64)                   // 1563

// fp16 transformed features, split into 2 column planes of 32:
// layout [(plane*8 + r) * N_NODES + n] * 32 + c   (each plane 51.2 MB)
__device__ __half g_XWh[(size_t)2 * N_RELS * N_NODES * 32];
// fp16 transposed weights: g_Wht[r][n][k]
__device__ __half g_Wht[N_RELS * F_DIM * F_DIM];
// CSR-by-dst build
__device__ int g_count[N_NODES];
__device__ int g_tmp[N_NODES];
__device__ int g_start[N_NODES];
__device__ int g_rank[N_EDGES];
__device__ int g_blocktot[SCAN_NBLK];
// packed edge records grouped by dst: lo32 = src | (rel<<17), hi32 = bits(A)
__device__ __align__(16) unsigned long long g_recs[N_EDGES];

// ---------------------------------------------------------------------------
// Fused: histogram (stores rank) + W pre-convert/transpose
// ---------------------------------------------------------------------------
__global__ __launch_bounds__(256) void hist_wconv_kernel(const int* __restrict__ dst,
                                                         const float* __restrict__ W) {
    int bx = blockIdx.x;
    if (bx < EBLOCKS) {
        int e = bx * 256 + threadIdx.x;
        if (e < N_EDGES) {
            int p = atomicAdd(&g_count[dst[e]], 1);
            g_rank[e] = p;
        }
    } else {
        int i = (bx - EBLOCKS) * 256 + threadIdx.x;
        if (i < N_RELS * 64 * 64) {
            int r = i >> 12;
            int n = (i >> 6) & 63;
            int k = i & 63;
            g_Wht[i] = __float2half_rn(W[r * 4096 + k * 64 + n]);
        }
    }
}

// ---------------------------------------------------------------------------
// scan1: per-block inclusive scan of counts
// ---------------------------------------------------------------------------
__global__ __launch_bounds__(SCAN_BLK) void scan1_kernel() {
    __shared__ int s[SCAN_BLK];
    int t = threadIdx.x;
    int i = blockIdx.x * SCAN_BLK + t;
    int v = (i < N_NODES) ? g_count[i] : 0;
    s[t] = v;
    __syncthreads();
    for (int off = 1; off < SCAN_BLK; off <<= 1) {
        int add = (t >= off) ? s[t - off] : 0;
        __syncthreads();
        s[t] += add;
        __syncthreads();
    }
    if (i < N_NODES) g_tmp[i] = s[t];
    if (t == SCAN_BLK - 1) g_blocktot[blockIdx.x] = s[t];
}

// scan23: each block redundantly scans the 98 block totals, then writes starts
__global__ __launch_bounds__(SCAN_BLK) void scan23_kernel() {
    __shared__ int s[128];
    int t = threadIdx.x;
    if (t < 128) s[t] = (t < SCAN_NBLK) ? g_blocktot[t] : 0;
    __syncthreads();
    for (int off = 1; off < 128; off <<= 1) {
        int add = (t < 128 && t >= off) ? s[t - off] : 0;
        __syncthreads();
        if (t < 128) s[t] += add;
        __syncthreads();
    }
    int boff = s[blockIdx.x] - g_blocktot[blockIdx.x];   // exclusive offset
    int i = blockIdx.x * SCAN_BLK + t;
    if (i < N_NODES) g_start[i] = g_tmp[i] - g_count[i] + boff;
}

// ---------------------------------------------------------------------------
// Fused: atomic-free record scatter + XW GEMM (plane-split stores)
// ---------------------------------------------------------------------------
__global__ __launch_bounds__(256) void scatter_xw_kernel(const float* __restrict__ A,
                                                         const int* __restrict__ src,
                                                         const int* __restrict__ dst,
                                                         const int* __restrict__ etype,
                                                         const float* __restrict__ X,
                                                         __half* __restrict__ XWh) {
    __shared__ __half Xh[64][72];
    __shared__ __half Wt[64][72];

    int bx = blockIdx.x;
    if (bx >= XW_BLOCKS) {
        // ---- scatter path (no atomics) ----
        int e = (bx - XW_BLOCKS) * 256 + threadIdx.x;
        if (e >= N_EDGES) return;
        int d = dst[e];
        int p = g_start[d] + g_rank[e];
        unsigned key = (unsigned)src[e] | ((unsigned)etype[e] << 17);
        unsigned long long rec = (unsigned long long)key |
                                 ((unsigned long long)__float_as_uint(A[e]) << 32);
        g_recs[p] = rec;
        return;
    }

    // ---- xw path ----
    const int n0blk = bx * 64;

    for (int i = threadIdx.x; i < 64 * 32; i += 256) {
        int row = i >> 5, cp = i & 31;
        int n = n0blk + row;
        float2 v = (n < N_NODES)
            ? *reinterpret_cast<const float2*>(X + (size_t)n * 64 + cp * 2)
            : make_float2(0.0f, 0.0f);
        *reinterpret_cast<__half2*>(&Xh[row][cp * 2]) = __floats2half2_rn(v.x, v.y);
    }

    const int warp = threadIdx.x >> 5;
    const int lane = threadIdx.x & 31;
    const int g = lane >> 2;
    const int t = lane & 3;
    const int r0 = (warp & 3) * 16;
    const int ch = (warp >> 2) * 32;      // column half = plane
    const int plane = ch >> 5;

    for (int r = 0; r < N_RELS; r++) {
        __syncthreads();
        for (int i = threadIdx.x; i < 64 * 32; i += 256) {
            int n = i >> 5, kp = i & 31;
            *reinterpret_cast<__half2*>(&Wt[n][kp * 2]) =
                *reinterpret_cast<const __half2*>(&g_Wht[r * 4096 + n * 64 + kp * 2]);
        }
        __syncthreads();

        float acc[4][4];
#pragma unroll
        for (int j = 0; j < 4; j++)
#pragma unroll
            for (int c = 0; c < 4; c++) acc[j][c] = 0.0f;

#pragma unroll
        for (int kk = 0; kk < 4; kk++) {
            const int k0 = kk * 16;
            uint32_t a0 = *reinterpret_cast<const uint32_t*>(&Xh[r0 + g    ][k0 + 2 * t    ]);
            uint32_t a1 = *reinterpret_cast<const uint32_t*>(&Xh[r0 + g + 8][k0 + 2 * t    ]);
            uint32_t a2 = *reinterpret_cast<const uint32_t*>(&Xh[r0 + g    ][k0 + 2 * t + 8]);
            uint32_t a3 = *reinterpret_cast<const uint32_t*>(&Xh[r0 + g + 8][k0 + 2 * t + 8]);
#pragma unroll
            for (int j = 0; j < 4; j++) {
                const int n0 = ch + j * 8;
                uint32_t b0 = *reinterpret_cast<const uint32_t*>(&Wt[n0 + g][k0 + 2 * t    ]);
                uint32_t b1 = *reinterpret_cast<const uint32_t*>(&Wt[n0 + g][k0 + 2 * t + 8]);
                asm volatile(
                    "mma.sync.aligned.m16n8k16.row.col.f32.f16.f16.f32 "
                    "{%0,%1,%2,%3}, {%4,%5,%6,%7}, {%8,%9}, {%0,%1,%2,%3};"
                    : "+f"(acc[j][0]), "+f"(acc[j][1]), "+f"(acc[j][2]), "+f"(acc[j][3])
                    : "r"(a0), "r"(a1), "r"(a2), "r"(a3), "r"(b0), "r"(b1));
            }
        }

        // Store into plane table: [(plane*8 + r) * N + n]*32 + colp
        __half* base = XWh + ((size_t)(plane * N_RELS + r) * N_NODES) * 32;
#pragma unroll
        for (int j = 0; j < 4; j++) {
            const int colp = j * 8 + 2 * t;          // 0..30 within plane
            const int row_a = n0blk + r0 + g;
            const int row_b = row_a + 8;
            __half2 lo = __floats2half2_rn(acc[j][0], acc[j][1]);
            __half2 hi = __floats2half2_rn(acc[j][2], acc[j][3]);
            if (row_a < N_NODES)
                *reinterpret_cast<__half2*>(base + (size_t)row_a * 32 + colp) = lo;
            if (row_b < N_NODES)
                *reinterpret_cast<__half2*>(base + (size_t)row_b * 32 + colp) = hi;
        }
    }
}

// ---------------------------------------------------------------------------
// Gather pass over ONE 51.2MB plane (L2-resident). Warp-per-node; lane L
// serves edge base+(L>>3), 4 halves at cols 4*(L&7). One warp LDG covers
// 4 edges' 64B plane-rows. Branch-free hot loop; shuffles only at node end.
// ---------------------------------------------------------------------------
__global__ __launch_bounds__(256) void gather_pass_kernel(const __half* __restrict__ plane,
                                                          float* __restrict__ Y,
                                                          int colbase) {
    const int node = blockIdx.x * 8 + (threadIdx.x >> 5);
    if (node >= N_NODES) return;
    const int lane = threadIdx.x & 31;
    const int sub  = lane >> 3;          // which edge in group of 4
    const int c4   = (lane & 7) * 4;     // starting half-column within plane

    const int s = g_start[node];
    const int end = s + g_count[node];

    float acc[4];
#pragma unroll
    for (int j = 0; j < 4; j++) acc[j] = 0.0f;

    int i = s;
    // Peel one edge if start odd (align record uint4 reads); sub0 contributes
    if ((i & 1) && i < end) {
        unsigned long long r0 = g_recs[i];
        unsigned k0 = (unsigned)r0;
        float a0 = (sub == 0) ? __uint_as_float((unsigned)(r0 >> 32)) : 0.0f;
        size_t row = (size_t)(k0 >> 17) * N_NODES + (k0 & 0x1FFFF);
        uint2 h = *reinterpret_cast<const uint2*>(plane + row * 32 + c4);
        const __half2* p = reinterpret_cast<const __half2*>(&h);
#pragma unroll
        for (int j = 0; j < 2; j++) {
            float2 f = __half22float2(p[j]);
            acc[2 * j]     = fmaf(f.x, a0, acc[2 * j]);
            acc[2 * j + 1] = fmaf(f.y, a0, acc[2 * j + 1]);
        }
        i++;
    }

    for (; i + 8 <= end; i += 8) {
        uint4 ra0 = *reinterpret_cast<const uint4*>(g_recs + i);
        uint4 rb0 = *reinterpret_cast<const uint4*>(g_recs + i + 2);
        uint4 ra1 = *reinterpret_cast<const uint4*>(g_recs + i + 4);
        uint4 rb1 = *reinterpret_cast<const uint4*>(g_recs + i + 6);

        unsigned k0 = sub == 0 ? ra0.x : sub == 1 ? ra0.z : sub == 2 ? rb0.x : rb0.z;
        float    a0 = __uint_as_float(sub == 0 ? ra0.y : sub == 1 ? ra0.w
                                    : sub == 2 ? rb0.y : rb0.w);
        unsigned k1 = sub == 0 ? ra1.x : sub == 1 ? ra1.z : sub == 2 ? rb1.x : rb1.z;
        float    a1 = __uint_as_float(sub == 0 ? ra1.y : sub == 1 ? ra1.w
                                    : sub == 2 ? rb1.y : rb1.w);

        size_t row0 = (size_t)(k0 >> 17) * N_NODES + (k0 & 0x1FFFF);
        size_t row1 = (size_t)(k1 >> 17) * N_NODES + (k1 & 0x1FFFF);
        uint2 h0 = *reinterpret_cast<const uint2*>(plane + row0 * 32 + c4);
        uint2 h1 = *reinterpret_cast<const uint2*>(plane + row1 * 32 + c4);

        const __half2* p0 = reinterpret_cast<const __half2*>(&h0);
        const __half2* p1 = reinterpret_cast<const __half2*>(&h1);
#pragma unroll
        for (int j = 0; j < 2; j++) {
            float2 f0 = __half22float2(p0[j]);
            float2 f1 = __half22float2(p1[j]);
            acc[2 * j]     = fmaf(f0.x, a0, acc[2 * j]);
            acc[2 * j + 1] = fmaf(f0.y, a0, acc[2 * j + 1]);
            acc[2 * j]     = fmaf(f1.x, a1, acc[2 * j]);
            acc[2 * j + 1] = fmaf(f1.y, a1, acc[2 * j + 1]);
        }
    }

    // Remainder: masked groups of up to 4 edges (branch-free loads of row 0)
    for (; i < end; i += 4) {
        int m = end - i;
        bool v = sub < m;
        unsigned long long r = v ? g_recs[i + sub] : 0ULL;
        unsigned k = (unsigned)r;
        float aa = v ? __uint_as_float((unsigned)(r >> 32)) : 0.0f;
        size_t row = (size_t)(k >> 17) * N_NODES + (k & 0x1FFFF);
        uint2 h = *reinterpret_cast<const uint2*>(plane + row * 32 + c4);
        const __half2* p = reinterpret_cast<const __half2*>(&h);
#pragma unroll
        for (int j = 0; j < 2; j++) {
            float2 f = __half22float2(p[j]);
            acc[2 * j]     = fmaf(f.x, aa, acc[2 * j]);
            acc[2 * j + 1] = fmaf(f.y, aa, acc[2 * j + 1]);
        }
    }

    // Combine 4 sub-group partials (lanes L, L^8, L^16, L^24)
#pragma unroll
    for (int j = 0; j < 4; j++) {
        acc[j] += __shfl_xor_sync(0xffffffffu, acc[j], 8);
        acc[j] += __shfl_xor_sync(0xffffffffu, acc[j], 16);
    }

    if (lane < 8) {
        *reinterpret_cast<float4*>(Y + (size_t)node * 64 + colbase + c4) =
            make_float4(acc[0], acc[1], acc[2], acc[3]);
    }
}

// ---------------------------------------------------------------------------
extern "C" void kernel_launch(void* const* d_in, const int* in_sizes, int n_in,
                              void* d_out, int out_size) {
    const float* X     = (const float*)d_in[0];
    const float* W     = (const float*)d_in[1];
    const float* A     = (const float*)d_in[2];
    const int*   src   = (const int*)d_in[3];
    const int*   dst   = (const int*)d_in[4];
    const int*   etype = (const int*)d_in[5];
    float* Y = (float*)d_out;

    __half* XWh = nullptr;
    cudaGetSymbolAddress((void**)&XWh, g_XWh);
    void* countp = nullptr;
    cudaGetSymbolAddress(&countp, g_count);

    cudaMemsetAsync(countp, 0, N_NODES * sizeof(int), 0);

    hist_wconv_kernel<<<EBLOCKS + WCONV_BLOCKS, 256>>>(dst, W);
    scan1_kernel<<<SCAN_NBLK, SCAN_BLK>>>();
    scan23_kernel<<<SCAN_NBLK, SCAN_BLK>>>();

    // atomic-free scatter + XW GEMM co-resident
    scatter_xw_kernel<<<XW_BLOCKS + EBLOCKS, 256>>>(A, src, dst, etype, X, XWh);

    // two L2-resident gather passes, one per 51.2MB plane
    const size_t plane_elems = (size_t)N_RELS * N_NODES * 32;
    gather_pass_kernel<<<(N_NODES + 7) / 8, 256>>>(XWh, Y, 0);
    gather_pass_kernel<<<(N_NODES + 7) / 8, 256>>>(XWh + plane_elems, Y, 32);
}

// round 15
// speedup vs baseline: 1.1053x; 1.1053x over previous
#include <cuda_runtime.h>
#include <cuda_fp16.h>
#include <cstdint>

#define N_NODES 100000
#define N_EDGES 3200000
#define N_RELS  8
#define F_DIM   64

#define SCAN_BLK 1024
#define SCAN_NBLK ((N_NODES + SCAN_BLK - 1) / SCAN_BLK)   // 98

#define EBLOCKS4 ((N_EDGES + 1023) / 1024)                // 3125 (4 edges/thread)
#define WCONV_BLOCKS ((N_RELS * 64 * 64 + 255) / 256)     // 128
#define XW_BLOCKS ((N_NODES + 63) / 64)                   // 1563

// fp16 per-relation transformed features: 102.4 MB, [r][n][64]
__device__ __half g_XWh[(size_t)N_RELS * N_NODES * F_DIM];
// fp16 transposed weights: g_Wht[r][n][k]
__device__ __half g_Wht[N_RELS * F_DIM * F_DIM];
// CSR-by-dst build
__device__ int g_count[N_NODES];
__device__ int g_tmp[N_NODES];
__device__ int g_start[N_NODES];
__device__ int g_rank[N_EDGES];
__device__ int g_blocktot[SCAN_NBLK];
// packed edge records grouped by dst: lo32 = src | (rel<<17), hi32 = bits(A)
__device__ __align__(16) unsigned long long g_recs[N_EDGES];

// ---------------------------------------------------------------------------
// Fused: histogram (4 edges/thread, stores rank) + W pre-convert/transpose
// ---------------------------------------------------------------------------
__global__ __launch_bounds__(256) void hist_wconv_kernel(const int* __restrict__ dst,
                                                         const float* __restrict__ W) {
    int bx = blockIdx.x;
    if (bx < EBLOCKS4) {
        int e0 = (bx * 256 + threadIdx.x) * 4;
        if (e0 + 4 <= N_EDGES) {
            int4 d = *reinterpret_cast<const int4*>(dst + e0);
            int4 p;
            p.x = atomicAdd(&g_count[d.x], 1);
            p.y = atomicAdd(&g_count[d.y], 1);
            p.z = atomicAdd(&g_count[d.z], 1);
            p.w = atomicAdd(&g_count[d.w], 1);
            *reinterpret_cast<int4*>(g_rank + e0) = p;
        } else {
            for (int e = e0; e < N_EDGES; e++)
                g_rank[e] = atomicAdd(&g_count[dst[e]], 1);
        }
    } else {
        int i = (bx - EBLOCKS4) * 256 + threadIdx.x;
        if (i < N_RELS * 64 * 64) {
            int r = i >> 12;
            int n = (i >> 6) & 63;
            int k = i & 63;
            g_Wht[i] = __float2half_rn(W[r * 4096 + k * 64 + n]);
        }
    }
}

// ---------------------------------------------------------------------------
// scan1: per-block inclusive scan of counts
// ---------------------------------------------------------------------------
__global__ __launch_bounds__(SCAN_BLK) void scan1_kernel() {
    __shared__ int s[SCAN_BLK];
    int t = threadIdx.x;
    int i = blockIdx.x * SCAN_BLK + t;
    int v = (i < N_NODES) ? g_count[i] : 0;
    s[t] = v;
    __syncthreads();
    for (int off = 1; off < SCAN_BLK; off <<= 1) {
        int add = (t >= off) ? s[t - off] : 0;
        __syncthreads();
        s[t] += add;
        __syncthreads();
    }
    if (i < N_NODES) g_tmp[i] = s[t];
    if (t == SCAN_BLK - 1) g_blocktot[blockIdx.x] = s[t];
}

// scan23: each block redundantly scans block totals, then writes starts
__global__ __launch_bounds__(SCAN_BLK) void scan23_kernel() {
    __shared__ int s[128];
    int t = threadIdx.x;
    if (t < 128) s[t] = (t < SCAN_NBLK) ? g_blocktot[t] : 0;
    __syncthreads();
    for (int off = 1; off < 128; off <<= 1) {
        int add = (t < 128 && t >= off) ? s[t - off] : 0;
        __syncthreads();
        if (t < 128) s[t] += add;
        __syncthreads();
    }
    int boff = s[blockIdx.x] - g_blocktot[blockIdx.x];
    int i = blockIdx.x * SCAN_BLK + t;
    if (i < N_NODES) g_start[i] = g_tmp[i] - g_count[i] + boff;
}

// ---------------------------------------------------------------------------
// Fused: atomic-free 4-wide record scatter + XW GEMM
// ---------------------------------------------------------------------------
__global__ __launch_bounds__(256) void scatter_xw_kernel(const float* __restrict__ A,
                                                         const int* __restrict__ src,
                                                         const int* __restrict__ dst,
                                                         const int* __restrict__ etype,
                                                         const float* __restrict__ X,
                                                         __half* __restrict__ XWh) {
    __shared__ __half Xh[64][72];
    __shared__ __half Wt[64][72];

    int bx = blockIdx.x;
    if (bx >= XW_BLOCKS) {
        // ---- scatter path: 4 edges per thread, no atomics ----
        int e0 = ((bx - XW_BLOCKS) * 256 + threadIdx.x) * 4;
        if (e0 + 4 <= N_EDGES) {
            int4  d  = *reinterpret_cast<const int4*>(dst + e0);
            int4  rk = *reinterpret_cast<const int4*>(g_rank + e0);
            int4  sr = *reinterpret_cast<const int4*>(src + e0);
            int4  et = *reinterpret_cast<const int4*>(etype + e0);
            float4 aa = *reinterpret_cast<const float4*>(A + e0);
            int p0 = g_start[d.x] + rk.x;
            int p1 = g_start[d.y] + rk.y;
            int p2 = g_start[d.z] + rk.z;
            int p3 = g_start[d.w] + rk.w;
            g_recs[p0] = (unsigned long long)((unsigned)sr.x | ((unsigned)et.x << 17)) |
                         ((unsigned long long)__float_as_uint(aa.x) << 32);
            g_recs[p1] = (unsigned long long)((unsigned)sr.y | ((unsigned)et.y << 17)) |
                         ((unsigned long long)__float_as_uint(aa.y) << 32);
            g_recs[p2] = (unsigned long long)((unsigned)sr.z | ((unsigned)et.z << 17)) |
                         ((unsigned long long)__float_as_uint(aa.z) << 32);
            g_recs[p3] = (unsigned long long)((unsigned)sr.w | ((unsigned)et.w << 17)) |
                         ((unsigned long long)__float_as_uint(aa.w) << 32);
        } else {
            for (int e = e0; e < N_EDGES; e++) {
                int p = g_start[dst[e]] + g_rank[e];
                unsigned key = (unsigned)src[e] | ((unsigned)etype[e] << 17);
                g_recs[p] = (unsigned long long)key |
                            ((unsigned long long)__float_as_uint(A[e]) << 32);
            }
        }
        return;
    }

    // ---- xw path ----
    const int n0blk = bx * 64;

    for (int i = threadIdx.x; i < 64 * 32; i += 256) {
        int row = i >> 5, cp = i & 31;
        int n = n0blk + row;
        float2 v = (n < N_NODES)
            ? *reinterpret_cast<const float2*>(X + (size_t)n * 64 + cp * 2)
            : make_float2(0.0f, 0.0f);
        *reinterpret_cast<__half2*>(&Xh[row][cp * 2]) = __floats2half2_rn(v.x, v.y);
    }

    const int warp = threadIdx.x >> 5;
    const int lane = threadIdx.x & 31;
    const int g = lane >> 2;
    const int t = lane & 3;
    const int r0 = (warp & 3) * 16;
    const int ch = (warp >> 2) * 32;

    for (int r = 0; r < N_RELS; r++) {
        __syncthreads();
        for (int i = threadIdx.x; i < 64 * 32; i += 256) {
            int n = i >> 5, kp = i & 31;
            *reinterpret_cast<__half2*>(&Wt[n][kp * 2]) =
                *reinterpret_cast<const __half2*>(&g_Wht[r * 4096 + n * 64 + kp * 2]);
        }
        __syncthreads();

        float acc[4][4];
#pragma unroll
        for (int j = 0; j < 4; j++)
#pragma unroll
            for (int c = 0; c < 4; c++) acc[j][c] = 0.0f;

#pragma unroll
        for (int kk = 0; kk < 4; kk++) {
            const int k0 = kk * 16;
            uint32_t a0 = *reinterpret_cast<const uint32_t*>(&Xh[r0 + g    ][k0 + 2 * t    ]);
            uint32_t a1 = *reinterpret_cast<const uint32_t*>(&Xh[r0 + g + 8][k0 + 2 * t    ]);
            uint32_t a2 = *reinterpret_cast<const uint32_t*>(&Xh[r0 + g    ][k0 + 2 * t + 8]);
            uint32_t a3 = *reinterpret_cast<const uint32_t*>(&Xh[r0 + g + 8][k0 + 2 * t + 8]);
#pragma unroll
            for (int j = 0; j < 4; j++) {
                const int n0 = ch + j * 8;
                uint32_t b0 = *reinterpret_cast<const uint32_t*>(&Wt[n0 + g][k0 + 2 * t    ]);
                uint32_t b1 = *reinterpret_cast<const uint32_t*>(&Wt[n0 + g][k0 + 2 * t + 8]);
                asm volatile(
                    "mma.sync.aligned.m16n8k16.row.col.f32.f16.f16.f32 "
                    "{%0,%1,%2,%3}, {%4,%5,%6,%7}, {%8,%9}, {%0,%1,%2,%3};"
                    : "+f"(acc[j][0]), "+f"(acc[j][1]), "+f"(acc[j][2]), "+f"(acc[j][3])
                    : "r"(a0), "r"(a1), "r"(a2), "r"(a3), "r"(b0), "r"(b1));
            }
        }

        __half* base = XWh + (size_t)r * N_NODES * 64;
#pragma unroll
        for (int j = 0; j < 4; j++) {
            const int col = ch + j * 8 + 2 * t;
            const int row_a = n0blk + r0 + g;
            const int row_b = row_a + 8;
            __half2 lo = __floats2half2_rn(acc[j][0], acc[j][1]);
            __half2 hi = __floats2half2_rn(acc[j][2], acc[j][3]);
            if (row_a < N_NODES)
                *reinterpret_cast<__half2*>(base + (size_t)row_a * 64 + col) = lo;
            if (row_b < N_NODES)
                *reinterpret_cast<__half2*>(base + (size_t)row_b * 64 + col) = hi;
        }
    }
}

// ---------------------------------------------------------------------------
// Gather (R12 winner): warp-per-node, 8-edge unroll, record pairs via LDG.128
// ---------------------------------------------------------------------------
__global__ __launch_bounds__(256) void gather_kernel(const __half* __restrict__ XWh,
                                                     float* __restrict__ Y) {
    const int node = blockIdx.x * 8 + (threadIdx.x >> 5);
    if (node >= N_NODES) return;
    const int lane = threadIdx.x & 31;

    const int s = g_start[node];
    const int end = s + g_count[node];

    float acc0 = 0.0f, acc1 = 0.0f;

    int i = s;
    if ((i & 1) && i < end) {
        unsigned long long r0 = g_recs[i];
        unsigned k0 = (unsigned)r0;
        float a0 = __uint_as_float((unsigned)(r0 >> 32));
        size_t row0 = (size_t)(k0 >> 17) * N_NODES + (k0 & 0x1FFFF);
        __half2 h0 = *(reinterpret_cast<const __half2*>(XWh + row0 * 64) + lane);
        float2 f0 = __half22float2(h0);
        acc0 = fmaf(f0.x, a0, acc0);
        acc1 = fmaf(f0.y, a0, acc1);
        i++;
    }

    for (; i + 8 <= end; i += 8) {
        uint4 rp[4];
#pragma unroll
        for (int q = 0; q < 4; q++)
            rp[q] = *reinterpret_cast<const uint4*>(g_recs + i + 2 * q);

        float2 f[8];
        float a[8];
#pragma unroll
        for (int q = 0; q < 4; q++) {
            unsigned ka = rp[q].x;
            unsigned kb = rp[q].z;
            a[2 * q]     = __uint_as_float(rp[q].y);
            a[2 * q + 1] = __uint_as_float(rp[q].w);
            size_t rowa = (size_t)(ka >> 17) * N_NODES + (ka & 0x1FFFF);
            size_t rowb = (size_t)(kb >> 17) * N_NODES + (kb & 0x1FFFF);
            __half2 ha = *(reinterpret_cast<const __half2*>(XWh + rowa * 64) + lane);
            __half2 hb = *(reinterpret_cast<const __half2*>(XWh + rowb * 64) + lane);
            f[2 * q]     = __half22float2(ha);
            f[2 * q + 1] = __half22float2(hb);
        }
#pragma unroll
        for (int q = 0; q < 8; q++) {
            acc0 = fmaf(f[q].x, a[q], acc0);
            acc1 = fmaf(f[q].y, a[q], acc1);
        }
    }
    for (; i < end; i++) {
        unsigned long long r0 = g_recs[i];
        unsigned k0 = (unsigned)r0;
        float a0 = __uint_as_float((unsigned)(r0 >> 32));
        size_t row0 = (size_t)(k0 >> 17) * N_NODES + (k0 & 0x1FFFF);
        __half2 h0 = *(reinterpret_cast<const __half2*>(XWh + row0 * 64) + lane);
        float2 f0 = __half22float2(h0);
        acc0 = fmaf(f0.x, a0, acc0);
        acc1 = fmaf(f0.y, a0, acc1);
    }

    *reinterpret_cast<float2*>(Y + (size_t)node * 64 + 2 * lane) =
        make_float2(acc0, acc1);
}

// ---------------------------------------------------------------------------
extern "C" void kernel_launch(void* const* d_in, const int* in_sizes, int n_in,
                              void* d_out, int out_size) {
    const float* X     = (const float*)d_in[0];
    const float* W     = (const float*)d_in[1];
    const float* A     = (const float*)d_in[2];
    const int*   src   = (const int*)d_in[3];
    const int*   dst   = (const int*)d_in[4];
    const int*   etype = (const int*)d_in[5];
    float* Y = (float*)d_out;

    __half* XWh = nullptr;
    cudaGetSymbolAddress((void**)&XWh, g_XWh);
    void* countp = nullptr;
    cudaGetSymbolAddress(&countp, g_count);

    cudaMemsetAsync(countp, 0, N_NODES * sizeof(int), 0);

    hist_wconv_kernel<<<EBLOCKS4 + WCONV_BLOCKS, 256>>>(dst, W);
    scan1_kernel<<<SCAN_NBLK, SCAN_BLK>>>();
    scan23_kernel<<<SCAN_NBLK, SCAN_BLK>>>();

    // atomic-free 4-wide scatter + XW GEMM co-resident
    scatter_xw_kernel<<<XW_BLOCKS + EBLOCKS4, 256>>>(A, src, dst, etype, X, XWh);

    // warp-per-node gather (writes every Y element; no memset needed)
    gather_kernel<<<(N_NODES + 7) / 8, 256>>>(XWh, Y);
}

// round 16
// speedup vs baseline: 1.1471x; 1.0378x over previous
#include <cuda_runtime.h>
#include <cuda_fp16.h>
#include <cstdint>

#define N_NODES 100000
#define N_EDGES 3200000
#define N_RELS  8
#define F_DIM   64

#define SCAN_BLK 1024
#define SCAN_NBLK ((N_NODES + SCAN_BLK - 1) / SCAN_BLK)   // 98

#define EBLOCKS ((N_EDGES + 255) / 256)                   // 12500
#define WCONV_BLOCKS ((N_RELS * 64 * 64 + 255) / 256)     // 128
#define XW_BLOCKS ((N_NODES + 63) / 64)                   // 1563

// fp16 per-relation transformed features: 102.4 MB, [r][n][64]
__device__ __half g_XWh[(size_t)N_RELS * N_NODES * F_DIM];
// fp16 transposed weights: g_Wht[r][n][k]
__device__ __half g_Wht[N_RELS * F_DIM * F_DIM];
// CSR-by-dst build
__device__ int g_count[N_NODES];
__device__ int g_tmp[N_NODES];
__device__ int g_start[N_NODES];
__device__ int g_rank[N_EDGES];
__device__ int g_blocktot[SCAN_NBLK];
// packed edge records grouped by dst: lo32 = src | (rel<<17), hi32 = bits(A)
__device__ __align__(16) unsigned long long g_recs[N_EDGES];

// ---------------------------------------------------------------------------
// Histogram over dst, storing each edge's rank within its dst
// ---------------------------------------------------------------------------
__global__ __launch_bounds__(256) void hist_kernel(const int* __restrict__ dst) {
    int e = blockIdx.x * 256 + threadIdx.x;
    if (e < N_EDGES) {
        g_rank[e] = atomicAdd(&g_count[dst[e]], 1);
    }
}

// ---------------------------------------------------------------------------
// W pre-convert + transpose: g_Wht[r][n][k] = fp16(W[r][k][n])
// ---------------------------------------------------------------------------
__global__ __launch_bounds__(256) void wconv_kernel(const float* __restrict__ W) {
    int i = blockIdx.x * 256 + threadIdx.x;
    if (i >= N_RELS * 64 * 64) return;
    int r = i >> 12;
    int n = (i >> 6) & 63;
    int k = i & 63;
    g_Wht[i] = __float2half_rn(W[r * 4096 + k * 64 + n]);
}

// ---------------------------------------------------------------------------
// scan1: per-block inclusive scan of counts
// ---------------------------------------------------------------------------
__global__ __launch_bounds__(SCAN_BLK) void scan1_kernel() {
    __shared__ int s[SCAN_BLK];
    int t = threadIdx.x;
    int i = blockIdx.x * SCAN_BLK + t;
    int v = (i < N_NODES) ? g_count[i] : 0;
    s[t] = v;
    __syncthreads();
    for (int off = 1; off < SCAN_BLK; off <<= 1) {
        int add = (t >= off) ? s[t - off] : 0;
        __syncthreads();
        s[t] += add;
        __syncthreads();
    }
    if (i < N_NODES) g_tmp[i] = s[t];
    if (t == SCAN_BLK - 1) g_blocktot[blockIdx.x] = s[t];
}

// scan23: each block redundantly scans block totals, then writes starts
__global__ __launch_bounds__(SCAN_BLK) void scan23_kernel() {
    __shared__ int s[128];
    int t = threadIdx.x;
    if (t < 128) s[t] = (t < SCAN_NBLK) ? g_blocktot[t] : 0;
    __syncthreads();
    for (int off = 1; off < 128; off <<= 1) {
        int add = (t < 128 && t >= off) ? s[t - off] : 0;
        __syncthreads();
        if (t < 128) s[t] += add;
        __syncthreads();
    }
    int boff = s[blockIdx.x] - g_blocktot[blockIdx.x];
    int i = blockIdx.x * SCAN_BLK + t;
    if (i < N_NODES) g_start[i] = g_tmp[i] - g_count[i] + boff;
}

// ---------------------------------------------------------------------------
// Atomic-free record scatter (1 edge/thread)
// ---------------------------------------------------------------------------
__global__ __launch_bounds__(256) void scatter_kernel(const float* __restrict__ A,
                                                      const int* __restrict__ src,
                                                      const int* __restrict__ dst,
                                                      const int* __restrict__ etype) {
    int e = blockIdx.x * 256 + threadIdx.x;
    if (e >= N_EDGES) return;
    int p = g_start[dst[e]] + g_rank[e];
    unsigned key = (unsigned)src[e] | ((unsigned)etype[e] << 17);
    g_recs[p] = (unsigned long long)key |
                ((unsigned long long)__float_as_uint(A[e]) << 32);
}

// ---------------------------------------------------------------------------
// XW GEMM: XWh[r] = fp16(X @ W[r]) — one X tile load, loop over 8 relations
// ---------------------------------------------------------------------------
__global__ __launch_bounds__(256) void xw_kernel(const float* __restrict__ X,
                                                 __half* __restrict__ XWh) {
    const int n0blk = blockIdx.x * 64;

    __shared__ __half Xh[64][72];
    __shared__ __half Wt[64][72];

    for (int i = threadIdx.x; i < 64 * 32; i += 256) {
        int row = i >> 5, cp = i & 31;
        int n = n0blk + row;
        float2 v = (n < N_NODES)
            ? *reinterpret_cast<const float2*>(X + (size_t)n * 64 + cp * 2)
            : make_float2(0.0f, 0.0f);
        *reinterpret_cast<__half2*>(&Xh[row][cp * 2]) = __floats2half2_rn(v.x, v.y);
    }

    const int warp = threadIdx.x >> 5;
    const int lane = threadIdx.x & 31;
    const int g = lane >> 2;
    const int t = lane & 3;
    const int r0 = (warp & 3) * 16;
    const int ch = (warp >> 2) * 32;

    for (int r = 0; r < N_RELS; r++) {
        __syncthreads();
        for (int i = threadIdx.x; i < 64 * 32; i += 256) {
            int n = i >> 5, kp = i & 31;
            *reinterpret_cast<__half2*>(&Wt[n][kp * 2]) =
                *reinterpret_cast<const __half2*>(&g_Wht[r * 4096 + n * 64 + kp * 2]);
        }
        __syncthreads();

        float acc[4][4];
#pragma unroll
        for (int j = 0; j < 4; j++)
#pragma unroll
            for (int c = 0; c < 4; c++) acc[j][c] = 0.0f;

#pragma unroll
        for (int kk = 0; kk < 4; kk++) {
            const int k0 = kk * 16;
            uint32_t a0 = *reinterpret_cast<const uint32_t*>(&Xh[r0 + g    ][k0 + 2 * t    ]);
            uint32_t a1 = *reinterpret_cast<const uint32_t*>(&Xh[r0 + g + 8][k0 + 2 * t    ]);
            uint32_t a2 = *reinterpret_cast<const uint32_t*>(&Xh[r0 + g    ][k0 + 2 * t + 8]);
            uint32_t a3 = *reinterpret_cast<const uint32_t*>(&Xh[r0 + g + 8][k0 + 2 * t + 8]);
#pragma unroll
            for (int j = 0; j < 4; j++) {
                const int n0 = ch + j * 8;
                uint32_t b0 = *reinterpret_cast<const uint32_t*>(&Wt[n0 + g][k0 + 2 * t    ]);
                uint32_t b1 = *reinterpret_cast<const uint32_t*>(&Wt[n0 + g][k0 + 2 * t + 8]);
                asm volatile(
                    "mma.sync.aligned.m16n8k16.row.col.f32.f16.f16.f32 "
                    "{%0,%1,%2,%3}, {%4,%5,%6,%7}, {%8,%9}, {%0,%1,%2,%3};"
                    : "+f"(acc[j][0]), "+f"(acc[j][1]), "+f"(acc[j][2]), "+f"(acc[j][3])
                    : "r"(a0), "r"(a1), "r"(a2), "r"(a3), "r"(b0), "r"(b1));
            }
        }

        __half* base = XWh + (size_t)r * N_NODES * 64;
#pragma unroll
        for (int j = 0; j < 4; j++) {
            const int col = ch + j * 8 + 2 * t;
            const int row_a = n0blk + r0 + g;
            const int row_b = row_a + 8;
            __half2 lo = __floats2half2_rn(acc[j][0], acc[j][1]);
            __half2 hi = __floats2half2_rn(acc[j][2], acc[j][3]);
            if (row_a < N_NODES)
                *reinterpret_cast<__half2*>(base + (size_t)row_a * 64 + col) = lo;
            if (row_b < N_NODES)
                *reinterpret_cast<__half2*>(base + (size_t)row_b * 64 + col) = hi;
        }
    }
}

// ---------------------------------------------------------------------------
// Gather (R12 winner): warp-per-node, 8-edge unroll, record pairs via LDG.128
// ---------------------------------------------------------------------------
__global__ __launch_bounds__(256) void gather_kernel(const __half* __restrict__ XWh,
                                                     float* __restrict__ Y) {
    const int node = blockIdx.x * 8 + (threadIdx.x >> 5);
    if (node >= N_NODES) return;
    const int lane = threadIdx.x & 31;

    const int s = g_start[node];
    const int end = s + g_count[node];

    float acc0 = 0.0f, acc1 = 0.0f;

    int i = s;
    if ((i & 1) && i < end) {
        unsigned long long r0 = g_recs[i];
        unsigned k0 = (unsigned)r0;
        float a0 = __uint_as_float((unsigned)(r0 >> 32));
        size_t row0 = (size_t)(k0 >> 17) * N_NODES + (k0 & 0x1FFFF);
        __half2 h0 = *(reinterpret_cast<const __half2*>(XWh + row0 * 64) + lane);
        float2 f0 = __half22float2(h0);
        acc0 = fmaf(f0.x, a0, acc0);
        acc1 = fmaf(f0.y, a0, acc1);
        i++;
    }

    for (; i + 8 <= end; i += 8) {
        uint4 rp[4];
#pragma unroll
        for (int q = 0; q < 4; q++)
            rp[q] = *reinterpret_cast<const uint4*>(g_recs + i + 2 * q);

        float2 f[8];
        float a[8];
#pragma unroll
        for (int q = 0; q < 4; q++) {
            unsigned ka = rp[q].x;
            unsigned kb = rp[q].z;
            a[2 * q]     = __uint_as_float(rp[q].y);
            a[2 * q + 1] = __uint_as_float(rp[q].w);
            size_t rowa = (size_t)(ka >> 17) * N_NODES + (ka & 0x1FFFF);
            size_t rowb = (size_t)(kb >> 17) * N_NODES + (kb & 0x1FFFF);
            __half2 ha = *(reinterpret_cast<const __half2*>(XWh + rowa * 64) + lane);
            __half2 hb = *(reinterpret_cast<const __half2*>(XWh + rowb * 64) + lane);
            f[2 * q]     = __half22float2(ha);
            f[2 * q + 1] = __half22float2(hb);
        }
#pragma unroll
        for (int q = 0; q < 8; q++) {
            acc0 = fmaf(f[q].x, a[q], acc0);
            acc1 = fmaf(f[q].y, a[q], acc1);
        }
    }
    for (; i < end; i++) {
        unsigned long long r0 = g_recs[i];
        unsigned k0 = (unsigned)r0;
        float a0 = __uint_as_float((unsigned)(r0 >> 32));
        size_t row0 = (size_t)(k0 >> 17) * N_NODES + (k0 & 0x1FFFF);
        __half2 h0 = *(reinterpret_cast<const __half2*>(XWh + row0 * 64) + lane);
        float2 f0 = __half22float2(h0);
        acc0 = fmaf(f0.x, a0, acc0);
        acc1 = fmaf(f0.y, a0, acc1);
    }

    *reinterpret_cast<float2*>(Y + (size_t)node * 64 + 2 * lane) =
        make_float2(acc0, acc1);
}

// ---------------------------------------------------------------------------
// Launch: fork GEMM chain onto a side stream (parallel graph branch),
// CSR chain on the main stream, join before gather.
// ---------------------------------------------------------------------------
extern "C" void kernel_launch(void* const* d_in, const int* in_sizes, int n_in,
                              void* d_out, int out_size) {
    const float* X     = (const float*)d_in[0];
    const float* W     = (const float*)d_in[1];
    const float* A     = (const float*)d_in[2];
    const int*   src   = (const int*)d_in[3];
    const int*   dst   = (const int*)d_in[4];
    const int*   etype = (const int*)d_in[5];
    float* Y = (float*)d_out;

    __half* XWh = nullptr;
    cudaGetSymbolAddress((void**)&XWh, g_XWh);
    void* countp = nullptr;
    cudaGetSymbolAddress(&countp, g_count);

    cudaStream_t s2;
    cudaStreamCreateWithFlags(&s2, cudaStreamNonBlocking);
    cudaEvent_t evFork, evJoin;
    cudaEventCreateWithFlags(&evFork, cudaEventDisableTiming);
    cudaEventCreateWithFlags(&evJoin, cudaEventDisableTiming);

    // Fork point on the capture (default) stream
    cudaEventRecord(evFork, 0);
    cudaStreamWaitEvent(s2, evFork, 0);

    // --- side branch: GEMM chain (independent of CSR build) ---
    wconv_kernel<<<WCONV_BLOCKS, 256, 0, s2>>>(W);
    xw_kernel<<<XW_BLOCKS, 256, 0, s2>>>(X, XWh);
    cudaEventRecord(evJoin, s2);

    // --- main branch: CSR build chain ---
    cudaMemsetAsync(countp, 0, N_NODES * sizeof(int), 0);
    hist_kernel<<<EBLOCKS, 256>>>(dst);
    scan1_kernel<<<SCAN_NBLK, SCAN_BLK>>>();
    scan23_kernel<<<SCAN_NBLK, SCAN_BLK>>>();
    scatter_kernel<<<EBLOCKS, 256>>>(A, src, dst, etype);

    // Join: gather needs both branches
    cudaStreamWaitEvent(0, evJoin, 0);
    gather_kernel<<<(N_NODES + 7) / 8, 256>>>(XWh, Y);
}